// round 4
// baseline (speedup 1.0000x reference)
#include <cuda_runtime.h>
#include <cuda_bf16.h>
#include <cstdint>

// SequenceEmbedding: out[0][c][i][j] = one_hot(seq[i])[c]          for c in [0,4)
//                    out[0][c][i][j] = one_hot(seq[j])[c-4]        for c in [4,8)
// Output (1, 8, 4096, 4096) fp32 = 536.9 MB of pure stores; HBM-write-bound.
//
// R3: single-wave launch (512 blocks x 64 rows, all resident at once -> no
// wave quantization / transitions) + streaming (evict-first) stores.

#define SEQ_L   4096
#define NB      4
#define ROWS_PB 64          // rows per block
#define TPB     256         // threads per block

// Detect whether seq buffer is int64 or int32 (values in [0,4): odd 32-bit
// words of an int64 LE layout are all zero; FP prob 4^-64 for int32 data).
__device__ __forceinline__ bool seq_is_int64(const int* s32) {
    bool is64 = true;
#pragma unroll
    for (int k = 0; k < 64; k++) {
        if (s32[2 * k + 1] != 0) is64 = false;
    }
    return is64;
}

__device__ __forceinline__ int seq_at(const void* seq, int i, bool is64) {
    if (is64) return (int)((const long long*)seq)[i];
    return ((const int*)seq)[i];
}

__global__ void __launch_bounds__(TPB)
SequenceEmbedding_30923764532139_kernel(const void* __restrict__ seq,
                                        const float* __restrict__ bt,
                                        float* __restrict__ out) {
    const int bx = blockIdx.x;
    const int c  = bx >> 6;               // 64 blocks per channel, 8 channels
    const int i0 = (bx & 63) * ROWS_PB;   // first row handled by this block
    const int t  = threadIdx.x;

    const bool is64 = seq_is_int64((const int*)seq);

    float4* __restrict__ chan = (float4*)(out + (size_t)c * SEQ_L * SEQ_L);
    const int row_f4 = SEQ_L / 4;         // 1024 float4 per row

    if (c < NB) {
        // Row-splat channels: value constant along j, varies per row i.
#pragma unroll 4
        for (int r = 0; r < ROWS_PB; r++) {
            const int i = i0 + r;
            const float v = bt[seq_at(seq, i, is64) * NB + c];   // uniform, L1-hot
            const float4 vv = make_float4(v, v, v, v);
            float4* rowp = chan + (size_t)i * row_f4;
#pragma unroll
            for (int k = 0; k < 4; k++) {
                __stcs(rowp + t + k * TPB, vv);   // warp-contiguous 512B streaming stores
            }
        }
    } else {
        // Column-pattern channels: every row of the channel is identical.
        // Materialize this thread's 16 pattern floats once; replay 64 rows.
        const int cc = c - NB;
        float4 p[4];
#pragma unroll
        for (int k = 0; k < 4; k++) {
            const int j = 4 * (t + k * TPB);
            p[k].x = bt[seq_at(seq, j + 0, is64) * NB + cc];
            p[k].y = bt[seq_at(seq, j + 1, is64) * NB + cc];
            p[k].z = bt[seq_at(seq, j + 2, is64) * NB + cc];
            p[k].w = bt[seq_at(seq, j + 3, is64) * NB + cc];
        }
#pragma unroll 4
        for (int r = 0; r < ROWS_PB; r++) {
            float4* rowp = chan + (size_t)(i0 + r) * row_f4;
#pragma unroll
            for (int k = 0; k < 4; k++) {
                __stcs(rowp + t + k * TPB, p[k]);
            }
        }
    }
}

extern "C" void kernel_launch(void* const* d_in, const int* in_sizes, int n_in,
                              void* d_out, int out_size) {
    const void*  seq = d_in[0];                 // 4096 ids (int32 or int64; auto-detected)
    const float* bt  = (const float*)d_in[1];   // 4x4 identity table, fp32
    float*       out = (float*)d_out;           // (1, 8, 4096, 4096) fp32

    const int total_rows = 8 * SEQ_L;                    // 32768
    const int grid = total_rows / ROWS_PB;               // 512 blocks -> single wave
    SequenceEmbedding_30923764532139_kernel<<<grid, TPB>>>(seq, bt, out);
}

// round 6
// speedup vs baseline: 1.1819x; 1.1819x over previous
#include <cuda_runtime.h>
#include <cuda_bf16.h>
#include <cstdint>

// SequenceEmbedding: out[0][c][i][j] = one_hot(seq[i])[c]          for c in [0,4)
//                    out[0][c][i][j] = one_hot(seq[j])[c-4]        for c in [4,8)
// Output (1, 8, 4096, 4096) fp32 = 536.9 MB of pure stores; HBM-write-bound.
//
// R4: revert to R2 structure (plain stores). Raise store-stream concurrency:
// 4096 blocks x 8 rows, and force 6 blocks/SM via __launch_bounds__ minBlocks
// (R3 showed the body fits in 40 regs). R3 proved DRAM% tracks resident store
// concurrency, not wave count.

#define SEQ_L   4096
#define NB      4
#define ROWS_PB 8           // rows per block
#define TPB     256         // threads per block

// Detect whether seq buffer is int64 or int32 (values in [0,4): odd 32-bit
// words of an int64 LE layout are all zero; FP prob 4^-64 for int32 data).
__device__ __forceinline__ bool seq_is_int64(const int* s32) {
    bool is64 = true;
#pragma unroll
    for (int k = 0; k < 64; k++) {
        if (s32[2 * k + 1] != 0) is64 = false;
    }
    return is64;
}

__device__ __forceinline__ int seq_at(const void* seq, int i, bool is64) {
    if (is64) return (int)((const long long*)seq)[i];
    return ((const int*)seq)[i];
}

__global__ void __launch_bounds__(TPB, 6)
SequenceEmbedding_30923764532139_kernel(const void* __restrict__ seq,
                                        const float* __restrict__ bt,
                                        float* __restrict__ out) {
    const int bx = blockIdx.x;
    const int c  = bx >> 9;                // 512 blocks per channel, 8 channels
    const int i0 = (bx & 511) * ROWS_PB;   // first row handled by this block
    const int t  = threadIdx.x;

    const bool is64 = seq_is_int64((const int*)seq);

    float4* __restrict__ chan = (float4*)(out + (size_t)c * SEQ_L * SEQ_L);
    const int row_f4 = SEQ_L / 4;          // 1024 float4 per row

    if (c < NB) {
        // Row-splat channels: value constant along j, varies per row i.
#pragma unroll
        for (int r = 0; r < ROWS_PB; r++) {
            const int i = i0 + r;
            const float v = bt[seq_at(seq, i, is64) * NB + c];   // uniform, L1-hot
            const float4 vv = make_float4(v, v, v, v);
            float4* rowp = chan + (size_t)i * row_f4;
#pragma unroll
            for (int k = 0; k < 4; k++) {
                rowp[t + k * TPB] = vv;    // warp-contiguous 512B stores
            }
        }
    } else {
        // Column-pattern channels: every row of the channel is identical.
        // Materialize this thread's 16 pattern floats once; replay 8 rows.
        const int cc = c - NB;
        float4 p[4];
#pragma unroll
        for (int k = 0; k < 4; k++) {
            const int j = 4 * (t + k * TPB);
            p[k].x = bt[seq_at(seq, j + 0, is64) * NB + cc];
            p[k].y = bt[seq_at(seq, j + 1, is64) * NB + cc];
            p[k].z = bt[seq_at(seq, j + 2, is64) * NB + cc];
            p[k].w = bt[seq_at(seq, j + 3, is64) * NB + cc];
        }
#pragma unroll
        for (int r = 0; r < ROWS_PB; r++) {
            float4* rowp = chan + (size_t)(i0 + r) * row_f4;
#pragma unroll
            for (int k = 0; k < 4; k++) {
                rowp[t + k * TPB] = p[k];
            }
        }
    }
}

extern "C" void kernel_launch(void* const* d_in, const int* in_sizes, int n_in,
                              void* d_out, int out_size) {
    const void*  seq = d_in[0];                 // 4096 ids (int32 or int64; auto-detected)
    const float* bt  = (const float*)d_in[1];   // 4x4 identity table, fp32
    float*       out = (float*)d_out;           // (1, 8, 4096, 4096) fp32

    const int total_rows = 8 * SEQ_L;                    // 32768
    const int grid = total_rows / ROWS_PB;               // 4096 blocks
    SequenceEmbedding_30923764532139_kernel<<<grid, TPB>>>(seq, bt, out);
}

// round 7
// speedup vs baseline: 1.1871x; 1.0044x over previous
#include <cuda_runtime.h>
#include <cuda_bf16.h>
#include <cstdint>

// SequenceEmbedding: out[0][c][i][j] = one_hot(seq[i])[c]          for c in [0,4)
//                    out[0][c][i][j] = one_hot(seq[j])[c-4]        for c in [4,8)
// Output (1, 8, 4096, 4096) fp32 = 536.9 MB of pure stores; HBM-write-bound.
//
// R6: exact R4 structure (4096 blocks x 8 rows, 6 blocks/SM) with ONE change:
// __stcs (evict-first) streaming stores. Isolates the L2 dirty-line-drain
// hypothesis — R3 confounded stcs with a bad grid shape.

#define SEQ_L   4096
#define NB      4
#define ROWS_PB 8           // rows per block
#define TPB     256         // threads per block

// Detect whether seq buffer is int64 or int32 (values in [0,4): odd 32-bit
// words of an int64 LE layout are all zero; FP prob 4^-64 for int32 data).
__device__ __forceinline__ bool seq_is_int64(const int* s32) {
    bool is64 = true;
#pragma unroll
    for (int k = 0; k < 64; k++) {
        if (s32[2 * k + 1] != 0) is64 = false;
    }
    return is64;
}

__device__ __forceinline__ int seq_at(const void* seq, int i, bool is64) {
    if (is64) return (int)((const long long*)seq)[i];
    return ((const int*)seq)[i];
}

__global__ void __launch_bounds__(TPB, 6)
SequenceEmbedding_30923764532139_kernel(const void* __restrict__ seq,
                                        const float* __restrict__ bt,
                                        float* __restrict__ out) {
    const int bx = blockIdx.x;
    const int c  = bx >> 9;                // 512 blocks per channel, 8 channels
    const int i0 = (bx & 511) * ROWS_PB;   // first row handled by this block
    const int t  = threadIdx.x;

    const bool is64 = seq_is_int64((const int*)seq);

    float4* __restrict__ chan = (float4*)(out + (size_t)c * SEQ_L * SEQ_L);
    const int row_f4 = SEQ_L / 4;          // 1024 float4 per row

    if (c < NB) {
        // Row-splat channels: value constant along j, varies per row i.
#pragma unroll
        for (int r = 0; r < ROWS_PB; r++) {
            const int i = i0 + r;
            const float v = bt[seq_at(seq, i, is64) * NB + c];   // uniform, L1-hot
            const float4 vv = make_float4(v, v, v, v);
            float4* rowp = chan + (size_t)i * row_f4;
#pragma unroll
            for (int k = 0; k < 4; k++) {
                __stcs(rowp + t + k * TPB, vv);   // evict-first streaming store
            }
        }
    } else {
        // Column-pattern channels: every row of the channel is identical.
        // Materialize this thread's 16 pattern floats once; replay 8 rows.
        const int cc = c - NB;
        float4 p[4];
#pragma unroll
        for (int k = 0; k < 4; k++) {
            const int j = 4 * (t + k * TPB);
            p[k].x = bt[seq_at(seq, j + 0, is64) * NB + cc];
            p[k].y = bt[seq_at(seq, j + 1, is64) * NB + cc];
            p[k].z = bt[seq_at(seq, j + 2, is64) * NB + cc];
            p[k].w = bt[seq_at(seq, j + 3, is64) * NB + cc];
        }
#pragma unroll
        for (int r = 0; r < ROWS_PB; r++) {
            float4* rowp = chan + (size_t)(i0 + r) * row_f4;
#pragma unroll
            for (int k = 0; k < 4; k++) {
                __stcs(rowp + t + k * TPB, p[k]);
            }
        }
    }
}

extern "C" void kernel_launch(void* const* d_in, const int* in_sizes, int n_in,
                              void* d_out, int out_size) {
    const void*  seq = d_in[0];                 // 4096 ids (int32 or int64; auto-detected)
    const float* bt  = (const float*)d_in[1];   // 4x4 identity table, fp32
    float*       out = (float*)d_out;           // (1, 8, 4096, 4096) fp32

    const int total_rows = 8 * SEQ_L;                    // 32768
    const int grid = total_rows / ROWS_PB;               // 4096 blocks
    SequenceEmbedding_30923764532139_kernel<<<grid, TPB>>>(seq, bt, out);
}